// round 7
// baseline (speedup 1.0000x reference)
#include <cuda_runtime.h>
#include <cstdint>

// N=100000 candidates, OBS=16, FEAT=96 -> ROW=1536 floats per candidate.
// target_vels row = 25*96 = 2400 floats.
#define ROW_F       1536
#define ROW_F4      (ROW_F / 4)       // 384 float4
#define F4_PER_LANE (ROW_F4 / 32)     // 12
#define OUT_F       2400
#define WARPS_PER_BLOCK 8
#define CANDS_PER_WARP  2
#define CANDS_PER_BLOCK (WARPS_PER_BLOCK * CANDS_PER_WARP)   // 16
#define THREADS     256

// Statically initialized for the first (uncaptured) correctness call; the
// gather kernel (last in stream order) resets it after use, so every graph
// replay starts clean.
__device__ unsigned long long g_best = 0xFFFFFFFFFFFFFFFFULL;

// Two candidates per warp: 24 independent LDG.128 in flight per warp body,
// halving the reduce/commit bubble rate. 6 blocks/SM floor (<=42 regs).
__global__ __launch_bounds__(THREADS, 6) void nn_dist_kernel(
    const float* __restrict__ in_pose,
    const float* __restrict__ train,
    int N)
{
    __shared__ float4 s_q[ROW_F4];
    __shared__ unsigned long long s_best[WARPS_PER_BLOCK];

    const int tid  = threadIdx.x;
    const int warp = tid >> 5;
    const int lane = tid & 31;

    // stage query (6 KB) into shared
    for (int i = tid; i < ROW_F4; i += THREADS)
        s_q[i] = reinterpret_cast<const float4*>(in_pose)[i];
    __syncthreads();

    const int c0 = blockIdx.x * CANDS_PER_BLOCK + warp * CANDS_PER_WARP;
    const int c1 = c0 + 1;
    unsigned long long best = 0xFFFFFFFFFFFFFFFFULL;

    if (c1 < N) {
        const float4* row0 = reinterpret_cast<const float4*>(train) + (size_t)c0 * ROW_F4;
        const float4* row1 = row0 + ROW_F4;
        float acc0 = 0.f, acc1 = 0.f;
        #pragma unroll
        for (int j = 0; j < F4_PER_LANE; j++) {
            const int idx = j * 32 + lane;
            float4 a = row0[idx];
            float4 b = row1[idx];
            float4 q = s_q[idx];
            float ax = a.x - q.x, ay = a.y - q.y, az = a.z - q.z, aw = a.w - q.w;
            float bx = b.x - q.x, by = b.y - q.y, bz = b.z - q.z, bw = b.w - q.w;
            acc0 += ax * ax + ay * ay + az * az + aw * aw;
            acc1 += bx * bx + by * by + bz * bz + bw * bw;
        }
        #pragma unroll
        for (int o = 16; o > 0; o >>= 1) {
            acc0 += __shfl_xor_sync(0xFFFFFFFFu, acc0, o);
            acc1 += __shfl_xor_sync(0xFFFFFFFFu, acc1, o);
        }
        // dist >= 0 -> IEEE bits order-preserving; low 32 = index, so u64 min
        // ties break to the SMALLEST index (jnp.argmin first-min semantics).
        unsigned long long p0 = ((unsigned long long)__float_as_uint(acc0) << 32) | (unsigned)c0;
        unsigned long long p1 = ((unsigned long long)__float_as_uint(acc1) << 32) | (unsigned)c1;
        best = min(p0, p1);
    } else if (c0 < N) {
        const float4* row0 = reinterpret_cast<const float4*>(train) + (size_t)c0 * ROW_F4;
        float acc0 = 0.f;
        #pragma unroll
        for (int j = 0; j < F4_PER_LANE; j++) {
            const int idx = j * 32 + lane;
            float4 a = row0[idx];
            float4 q = s_q[idx];
            float ax = a.x - q.x, ay = a.y - q.y, az = a.z - q.z, aw = a.w - q.w;
            acc0 += ax * ax + ay * ay + az * az + aw * aw;
        }
        #pragma unroll
        for (int o = 16; o > 0; o >>= 1)
            acc0 += __shfl_xor_sync(0xFFFFFFFFu, acc0, o);
        best = ((unsigned long long)__float_as_uint(acc0) << 32) | (unsigned)c0;
    }

    if (lane == 0) s_best[warp] = best;
    __syncthreads();

    // block reduce 8 -> 1, one global atomic per block
    if (tid == 0) {
        unsigned long long b = s_best[0];
        #pragma unroll
        for (int w = 1; w < WARPS_PER_BLOCK; w++) b = min(b, s_best[w]);
        atomicMin(&g_best, b);
    }
}

// Single block: gather the winning row (float4), then reset g_best.
__global__ void nn_gather_kernel(const float* __restrict__ target_vels,
                                 float* __restrict__ out)
{
    __shared__ unsigned int s_bestidx;
    if (threadIdx.x == 0)
        s_bestidx = (unsigned)(g_best & 0xFFFFFFFFULL);
    __syncthreads();

    const float4* src = reinterpret_cast<const float4*>(target_vels) + (size_t)s_bestidx * (OUT_F / 4);
    float4* dst = reinterpret_cast<float4*>(out);
    for (int i = threadIdx.x; i < OUT_F / 4; i += blockDim.x)
        dst[i] = src[i];

    __syncthreads();
    if (threadIdx.x == 0)
        g_best = 0xFFFFFFFFFFFFFFFFULL;   // clean state for next replay
}

extern "C" void kernel_launch(void* const* d_in, const int* in_sizes, int n_in,
                              void* d_out, int out_size)
{
    const float* in_pose     = (const float*)d_in[0];   // [16, 96]
    const float* train_poses = (const float*)d_in[1];   // [N, 16, 96]
    const float* target_vels = (const float*)d_in[2];   // [N, 25, 96]
    float* out = (float*)d_out;                          // [25, 96]

    const int N = in_sizes[1] / ROW_F;

    const int blocks = (N + CANDS_PER_BLOCK - 1) / CANDS_PER_BLOCK;
    nn_dist_kernel<<<blocks, THREADS>>>(in_pose, train_poses, N);
    nn_gather_kernel<<<1, 256>>>(target_vels, out);
}

// round 8
// speedup vs baseline: 1.0226x; 1.0226x over previous
#include <cuda_runtime.h>
#include <cstdint>

// N=100000 candidates, OBS=16, FEAT=96 -> ROW=1536 floats per candidate.
// target_vels row = 25*96 = 2400 floats.
#define ROW_F       1536
#define ROW_F4      (ROW_F / 4)       // 384 float4
#define F4_PER_LANE (ROW_F4 / 32)     // 12
#define OUT_F       2400
#define OUT_F4      (OUT_F / 4)       // 600
#define WARPS_PER_BLOCK 8

// Statically initialized for the first (uncaptured) correctness call; the
// gather kernel (last in dependency order) resets it after use, so every
// graph replay starts clean.
__device__ unsigned long long g_best = 0xFFFFFFFFFFFFFFFFULL;

// One warp per candidate; 8 warps/block; 32 regs -> full occupancy.
__global__ __launch_bounds__(256, 8) void nn_dist_kernel(
    const float* __restrict__ in_pose,
    const float* __restrict__ train,
    int N)
{
    __shared__ float4 s_q[ROW_F4];
    __shared__ unsigned long long s_best[WARPS_PER_BLOCK];

    const int tid  = threadIdx.x;
    const int warp = tid >> 5;
    const int lane = tid & 31;

    // stage query (6 KB) into shared
    for (int i = tid; i < ROW_F4; i += blockDim.x)
        s_q[i] = reinterpret_cast<const float4*>(in_pose)[i];
    __syncthreads();

    const int cand = blockIdx.x * WARPS_PER_BLOCK + warp;
    unsigned long long packed = 0xFFFFFFFFFFFFFFFFULL;

    if (cand < N) {
        const float4* row = reinterpret_cast<const float4*>(train) + (size_t)cand * ROW_F4;
        float acc = 0.f;
        #pragma unroll
        for (int j = 0; j < F4_PER_LANE; j++) {
            const int idx = j * 32 + lane;
            float4 a = row[idx];
            float4 q = s_q[idx];
            float dx = a.x - q.x;
            float dy = a.y - q.y;
            float dz = a.z - q.z;
            float dw = a.w - q.w;
            acc += dx * dx + dy * dy + dz * dz + dw * dw;
        }
        #pragma unroll
        for (int o = 16; o > 0; o >>= 1)
            acc += __shfl_xor_sync(0xFFFFFFFFu, acc, o);
        // acc >= 0 -> IEEE bits order-preserving; low 32 = index, so u64 min
        // ties break to the SMALLEST index (jnp.argmin first-min semantics).
        packed = ((unsigned long long)__float_as_uint(acc) << 32) | (unsigned)cand;
    }

    if (lane == 0) s_best[warp] = packed;
    __syncthreads();

    if (tid == 0) {
        unsigned long long b = s_best[0];
        #pragma unroll
        for (int w = 1; w < WARPS_PER_BLOCK; w++) b = min(b, s_best[w]);
        atomicMin(&g_best, b);
    }
    // Signal PDL: this block's contribution to g_best is committed.
    cudaTriggerProgrammaticLaunchCompletion();
}

// Launched with programmatic dependency: resident during the dist kernel,
// proceeds the instant all dist blocks have triggered (atomicMins visible).
__global__ void nn_gather_kernel(const float* __restrict__ target_vels,
                                 float* __restrict__ out)
{
    cudaGridDependencySynchronize();

    __shared__ unsigned int s_bestidx;
    if (threadIdx.x == 0)
        s_bestidx = (unsigned)(g_best & 0xFFFFFFFFULL);
    __syncthreads();

    const float4* src = reinterpret_cast<const float4*>(target_vels)
                        + (size_t)s_bestidx * OUT_F4;
    float4* dst = reinterpret_cast<float4*>(out);
    for (int i = threadIdx.x; i < OUT_F4; i += blockDim.x)
        dst[i] = src[i];

    __syncthreads();
    if (threadIdx.x == 0)
        g_best = 0xFFFFFFFFFFFFFFFFULL;   // clean state for next replay
}

extern "C" void kernel_launch(void* const* d_in, const int* in_sizes, int n_in,
                              void* d_out, int out_size)
{
    const float* in_pose     = (const float*)d_in[0];   // [16, 96]
    const float* train_poses = (const float*)d_in[1];   // [N, 16, 96]
    const float* target_vels = (const float*)d_in[2];   // [N, 25, 96]
    float* out = (float*)d_out;                          // [25, 96]

    const int N = in_sizes[1] / ROW_F;
    const int blocks = (N + WARPS_PER_BLOCK - 1) / WARPS_PER_BLOCK;

    nn_dist_kernel<<<blocks, 256>>>(in_pose, train_poses, N);

    // Gather with programmatic dependent launch: overlap its launch/prologue
    // with the dist kernel; it self-synchronizes via gridDependencySynchronize.
    cudaLaunchAttribute attrs[1];
    attrs[0].id = cudaLaunchAttributeProgrammaticStreamSerialization;
    attrs[0].val.programmaticStreamSerializationAllowed = 1;

    cudaLaunchConfig_t cfg = {};
    cfg.gridDim  = dim3(1, 1, 1);
    cfg.blockDim = dim3(256, 1, 1);
    cfg.dynamicSmemBytes = 0;
    cfg.stream = 0;
    cfg.attrs = attrs;
    cfg.numAttrs = 1;

    cudaLaunchKernelEx(&cfg, nn_gather_kernel, target_vels, out);
}